// round 16
// baseline (speedup 1.0000x reference)
#include <cuda_runtime.h>
#include <math.h>

#define NN 8192
#define DD 64
#define EE 524288
#define EP (EE + NN)   // edges + self loops

// ---------------- scratch (device globals) ----------------
__device__ float g_h  [NN*DD];
__device__ float g_xl [NN*DD];
__device__ float g_xr [NN*DD];
__device__ float g_M1 [DD*DD];
__device__ float g_M2 [DD*DD];
__device__ float g_c2 [DD];
__device__ float g_U  [NN*DD];
__device__ float g_V  [NN*DD];
__device__ int   g_deg[NN];
__device__ int   g_cnt[NN];
__device__ int   g_off[NN + 1];
__device__ int   g_soff[NN + 1];
__device__ int   g_ce [EP];        // dst-CSR: source node per slot

// ---------------- 64x64(xK) GEMM micro-kernel on smem tiles ----------------
template<int K>
__device__ __forceinline__ void gemmK(const float sx[64][K + 1], const float* sW,
                                      const float* __restrict__ b,
                                      int tx, int ty, float acc[4][4])
{
    const float4 bb = b ? ((const float4*)b)[tx] : make_float4(0.f, 0.f, 0.f, 0.f);
#pragma unroll
    for (int i = 0; i < 4; i++) {
        acc[i][0] = bb.x; acc[i][1] = bb.y; acc[i][2] = bb.z; acc[i][3] = bb.w;
    }
#pragma unroll
    for (int k = 0; k < K; k++) {
        const float4 w = ((const float4*)sW)[k * 16 + tx];
        const float x0 = sx[ty*4 + 0][k];
        const float x1 = sx[ty*4 + 1][k];
        const float x2 = sx[ty*4 + 2][k];
        const float x3 = sx[ty*4 + 3][k];
        acc[0][0] = fmaf(x0, w.x, acc[0][0]); acc[0][1] = fmaf(x0, w.y, acc[0][1]);
        acc[0][2] = fmaf(x0, w.z, acc[0][2]); acc[0][3] = fmaf(x0, w.w, acc[0][3]);
        acc[1][0] = fmaf(x1, w.x, acc[1][0]); acc[1][1] = fmaf(x1, w.y, acc[1][1]);
        acc[1][2] = fmaf(x1, w.z, acc[1][2]); acc[1][3] = fmaf(x1, w.w, acc[1][3]);
        acc[2][0] = fmaf(x2, w.x, acc[2][0]); acc[2][1] = fmaf(x2, w.y, acc[2][1]);
        acc[2][2] = fmaf(x2, w.z, acc[2][2]); acc[2][3] = fmaf(x2, w.w, acc[2][3]);
        acc[3][0] = fmaf(x3, w.x, acc[3][0]); acc[3][1] = fmaf(x3, w.y, acc[3][1]);
        acc[3][2] = fmaf(x3, w.z, acc[3][2]); acc[3][3] = fmaf(x3, w.w, acc[3][3]);
    }
}

// ---------------- input MLP, fused: h = relu(xW1+b1) ; h += relu(hW2+b2) ----------------
__global__ __launch_bounds__(256) void k_in(const float* __restrict__ x,
                                            const float* __restrict__ W1, const float* __restrict__ b1,
                                            const float* __restrict__ W2, const float* __restrict__ b2,
                                            float* __restrict__ h_out)
{
    __shared__ float sx[64][13];
    __shared__ float sW1[12 * 64];
    __shared__ float st[64][65];
    __shared__ float sW2[64 * 64];
    const int tid = threadIdx.x;
    const int tx = tid & 15, ty = tid >> 4;
    const int nb = blockIdx.x * 64;

    for (int i = tid; i < 192; i += 256) {
        const float4 v = ((const float4*)x)[nb * 3 + i];
        const int n = i / 3, k = (i % 3) * 4;
        sx[n][k] = v.x; sx[n][k+1] = v.y; sx[n][k+2] = v.z; sx[n][k+3] = v.w;
    }
    for (int i = tid; i < 192; i += 256) ((float4*)sW1)[i] = ((const float4*)W1)[i];
    for (int i = tid; i < 1024; i += 256) ((float4*)sW2)[i] = ((const float4*)W2)[i];
    __syncthreads();

    float acc[4][4];
    gemmK<12>(sx, sW1, b1, tx, ty, acc);
#pragma unroll
    for (int i = 0; i < 4; i++)
#pragma unroll
        for (int j = 0; j < 4; j++)
            st[ty*4 + i][tx*4 + j] = fmaxf(acc[i][j], 0.f);
    __syncthreads();

    float acc2[4][4];
    gemmK<64>(st, sW2, b2, tx, ty, acc2);
#pragma unroll
    for (int i = 0; i < 4; i++) {
        float4 r;
        r.x = st[ty*4+i][tx*4+0] + fmaxf(acc2[i][0], 0.f);
        r.y = st[ty*4+i][tx*4+1] + fmaxf(acc2[i][1], 0.f);
        r.z = st[ty*4+i][tx*4+2] + fmaxf(acc2[i][2], 0.f);
        r.w = st[ty*4+i][tx*4+3] + fmaxf(acc2[i][3], 0.f);
        ((float4*)h_out)[(nb + ty*4 + i) * 16 + tx] = r;
    }
}

// ---------------- fused: [h' = h + relu(hWa+ba)] ; xl = h'Wl+bl ; xr = h'Wr+br ----------------
template<bool PRE, bool WRITE_H>
__global__ __launch_bounds__(256) void k_fused3(
    const float* __restrict__ h_in,
    const float* __restrict__ Wa, const float* __restrict__ ba,
    const float* __restrict__ Wl, const float* __restrict__ bl,
    const float* __restrict__ Wr, const float* __restrict__ br,
    float* __restrict__ h_out, float* __restrict__ xl_out, float* __restrict__ xr_out)
{
    __shared__ float sh[64][65];
    __shared__ float sW[64 * 64];                  // staged: Wa -> Wl -> Wr
    const int tid = threadIdx.x;
    const int tx = tid & 15, ty = tid >> 4;
    const int nb = blockIdx.x * 64;

    for (int i = tid; i < 1024; i += 256) {
        const float4 v = ((const float4*)h_in)[nb * 16 + i];
        const int n = i >> 4, k = (i & 15) * 4;
        sh[n][k] = v.x; sh[n][k+1] = v.y; sh[n][k+2] = v.z; sh[n][k+3] = v.w;
    }

    if (PRE) {
        for (int i = tid; i < 1024; i += 256) ((float4*)sW)[i] = ((const float4*)Wa)[i];
        __syncthreads();
        float acc[4][4];
        gemmK<64>(sh, sW, ba, tx, ty, acc);
        float hp[4][4];
#pragma unroll
        for (int i = 0; i < 4; i++)
#pragma unroll
            for (int j = 0; j < 4; j++)
                hp[i][j] = sh[ty*4 + i][tx*4 + j] + fmaxf(acc[i][j], 0.f);
        __syncthreads();
#pragma unroll
        for (int i = 0; i < 4; i++) {
#pragma unroll
            for (int j = 0; j < 4; j++) sh[ty*4 + i][tx*4 + j] = hp[i][j];
            if (WRITE_H)
                ((float4*)h_out)[(nb + ty*4 + i) * 16 + tx] =
                    make_float4(hp[i][0], hp[i][1], hp[i][2], hp[i][3]);
        }
    }

    __syncthreads();
    for (int i = tid; i < 1024; i += 256) ((float4*)sW)[i] = ((const float4*)Wl)[i];
    __syncthreads();
    {
        float acc[4][4];
        gemmK<64>(sh, sW, bl, tx, ty, acc);
#pragma unroll
        for (int i = 0; i < 4; i++)
            ((float4*)xl_out)[(nb + ty*4 + i) * 16 + tx] =
                make_float4(acc[i][0], acc[i][1], acc[i][2], acc[i][3]);
    }
    __syncthreads();
    for (int i = tid; i < 1024; i += 256) ((float4*)sW)[i] = ((const float4*)Wr)[i];
    __syncthreads();
    {
        float acc[4][4];
        gemmK<64>(sh, sW, br, tx, ty, acc);
#pragma unroll
        for (int i = 0; i < 4; i++)
            ((float4*)xr_out)[(nb + ty*4 + i) * 16 + tx] =
                make_float4(acc[i][0], acc[i][1], acc[i][2], acc[i][3]);
    }
}

// ---------------- M1 = We1[:64]@We2, M2 = We1[64:]@We2, c2 = be1@We2 + be2 ----------------
__global__ __launch_bounds__(256) void k_prep(const float* __restrict__ We1,
                                              const float* __restrict__ be1,
                                              const float* __restrict__ We2,
                                              const float* __restrict__ be2)
{
    __shared__ float sW2[64 * 64];
    __shared__ float sA[4 * 64];
    __shared__ float sB[4 * 64];
    const int tid = threadIdx.x;
    const int kb = blockIdx.x * 4;
    for (int i = tid; i < 1024; i += 256) ((float4*)sW2)[i] = ((const float4*)We2)[i];
    {
        const int kk = tid >> 6, c = tid & 63;
        sA[tid] = We1[(kb + kk) * 64 + c];
        sB[tid] = We1[(64 + kb + kk) * 64 + c];
    }
    __syncthreads();
    const int kk = tid >> 6, c = tid & 63;
    float a1 = 0.f, a2 = 0.f;
#pragma unroll
    for (int j = 0; j < 64; j++) {
        const float w2 = sW2[j * 64 + c];
        a1 = fmaf(sA[kk * 64 + j], w2, a1);
        a2 = fmaf(sB[kk * 64 + j], w2, a2);
    }
    g_M1[(kb + kk) * 64 + c] = a1;
    g_M2[(kb + kk) * 64 + c] = a2;
    if (blockIdx.x == 0 && tid < 64) {
        float s = be2[tid];
        for (int j = 0; j < 64; j++) s = fmaf(be1[j], sW2[j * 64 + tid], s);
        g_c2[tid] = s;
    }
}

// ---------------- edge pass 0: dst histogram + src row offsets (src sorted) ----------------
__global__ void k_edge0(const int* __restrict__ src, const int* __restrict__ dst)
{
    const int e = blockIdx.x * blockDim.x + threadIdx.x;
    if (e >= EE) return;
    atomicAdd(&g_deg[dst[e]], 1);
    const int a = src[e];
    const int b = (e + 1 < EE) ? src[e + 1] : NN;
    for (int r = a + 1; r <= b; r++) g_soff[r] = e + 1;
    if (e == 0) for (int r = 0; r <= a; r++) g_soff[r] = 0;
}

__global__ __launch_bounds__(1024) void k_scan()
{
    __shared__ int wsum[32];
    const int tid = threadIdx.x;
    int loc[8]; int s = 0;
#pragma unroll
    for (int j = 0; j < 8; j++) {
        loc[j] = g_deg[tid * 8 + j] + 1; s += loc[j];     // +1 self loop
        g_cnt[tid * 8 + j] = 0;
    }
    const int lane = tid & 31, wid = tid >> 5;
    int v = s;
#pragma unroll
    for (int o = 1; o < 32; o <<= 1) {
        const int t = __shfl_up_sync(0xffffffffu, v, o);
        if (lane >= o) v += t;
    }
    if (lane == 31) wsum[wid] = v;
    __syncthreads();
    if (wid == 0) {
        int w = wsum[lane];
#pragma unroll
        for (int o = 1; o < 32; o <<= 1) {
            const int t = __shfl_up_sync(0xffffffffu, w, o);
            if (lane >= o) w += t;
        }
        wsum[lane] = w;
    }
    __syncthreads();
    int base = v - s + (wid ? wsum[wid - 1] : 0);
#pragma unroll
    for (int j = 0; j < 8; j++) { g_off[tid * 8 + j] = base; base += loc[j]; }
    if (tid == 1023) g_off[NN] = base;
}

__global__ void k_scatter(const int* __restrict__ src, const int* __restrict__ dst)
{
    const int e = blockIdx.x * blockDim.x + threadIdx.x;
    if (e >= EP) return;
    int s, d;
    if (e < EE) { s = src[e]; d = dst[e]; } else { s = d = e - EE; }
    const int pos = atomicAdd(&g_cnt[d], 1);
    g_ce[g_off[d] + pos] = s;
}

// ---------------- background output zeroing: 1 block/SM, leaves SMs free for co-run ----------
__global__ __launch_bounds__(256) void k_zero_out(float4* __restrict__ out)
{
    const long total = (long)NN * NN / 4;            // float4 count
    const long stride = (long)gridDim.x * 256;
    const float4 z = make_float4(0.f, 0.f, 0.f, 0.f);
    for (long i = (long)blockIdx.x * 256 + threadIdx.x; i < total; i += stride)
        __stcs(&out[i], z);
}

// ---------------- fused GATv2 layer: one warp per dst node, single pass, no atomics ----------------
__global__ __launch_bounds__(256) void k_gat(const float* __restrict__ att,
                                             const float* __restrict__ bo)
{
    const int w = (blockIdx.x * 256 + threadIdx.x) >> 5;   // grid covers NN exactly
    const int lane = threadIdx.x & 31;
    const int d = w;
    const float2 xr = ((const float2*)g_xr)[d * 32 + lane];
    const float2 a  = ((const float2*)att)[lane];
    const int beg = g_off[d], end = g_off[d + 1];   // warp-uniform
    float accx = 0.f, accy = 0.f, den = 0.f;
#pragma unroll 4
    for (int i = beg; i < end; i++) {
        const int s = g_ce[i];
        const float2 vl = ((const float2*)g_xl)[s * 32 + lane];
        float t0 = vl.x + xr.x; t0 = t0 > 0.f ? t0 : 0.2f * t0;
        float t1 = vl.y + xr.y; t1 = t1 > 0.f ? t1 : 0.2f * t1;
        float v = t0 * a.x + t1 * a.y;
        v += __shfl_xor_sync(0xffffffffu, v, 1);
        v += __shfl_xor_sync(0xffffffffu, v, 2);
        v += __shfl_xor_sync(0xffffffffu, v, 4);   // per-head logit in each 8-lane group
        const float pe = __expf(v);                // softmax shift-invariant; logits small
        den  += pe;
        accx = fmaf(pe, vl.x, accx);
        accy = fmaf(pe, vl.y, accy);
    }
    const float inv = 1.0f / den;
    const int idx = d * 64 + 2 * lane;
    g_h[idx]     += accx * inv + bo[2 * lane];
    g_h[idx + 1] += accy * inv + bo[2 * lane + 1];
}

// ---------------- final: one 16-lane group per edge, scattered write into pre-zeroed out ----
// EE divisible by 16 -> every group has exactly one edge; no loops, no predication.
__global__ __launch_bounds__(256) void k_final_e(const int* __restrict__ src,
                                                 const int* __restrict__ dst,
                                                 const float* __restrict__ We3,
                                                 const float* __restrict__ be3,
                                                 float* __restrict__ out)
{
    const int tid = threadIdx.x;
    const int e = blockIdx.x * 16 + (tid >> 4);
    const int l = tid & 15;
    const int s = src[e], d = dst[e];
    const float4 u  = ((const float4*)g_U)[s * 16 + l];   // src-sorted: strong L1 reuse
    const float4 vv = ((const float4*)g_V)[d * 16 + l];
    const float4 w3 = ((const float4*)We3)[l];
    float v = fmaxf(u.x + vv.x, 0.f) * w3.x
            + fmaxf(u.y + vv.y, 0.f) * w3.y
            + fmaxf(u.z + vv.z, 0.f) * w3.z
            + fmaxf(u.w + vv.w, 0.f) * w3.w;
    v += __shfl_xor_sync(0xffffffffu, v, 1);
    v += __shfl_xor_sync(0xffffffffu, v, 2);
    v += __shfl_xor_sync(0xffffffffu, v, 4);
    v += __shfl_xor_sync(0xffffffffu, v, 8);   // reduce within 16-lane group
    if (l == 0)
        out[(long)s * NN + d] = 1.0f / (1.0f + __expf(-(v + be3[0])));
}

// ---------------- host ----------------
extern "C" void kernel_launch(void* const* d_in, const int* in_sizes, int n_in,
                              void* d_out, int out_size)
{
    const float* x    = (const float*)d_in[0];
    const float* W1   = (const float*)d_in[1];
    const float* b1   = (const float*)d_in[2];
    const float* W2   = (const float*)d_in[3];
    const float* b2   = (const float*)d_in[4];
    const float* Wl1  = (const float*)d_in[5];
    const float* bl1  = (const float*)d_in[6];
    const float* Wr1  = (const float*)d_in[7];
    const float* br1  = (const float*)d_in[8];
    const float* att1 = (const float*)d_in[9];
    const float* bo1  = (const float*)d_in[10];
    const float* W4   = (const float*)d_in[11];
    const float* b4   = (const float*)d_in[12];
    const float* Wl2  = (const float*)d_in[13];
    const float* bl2  = (const float*)d_in[14];
    const float* Wr2  = (const float*)d_in[15];
    const float* br2  = (const float*)d_in[16];
    const float* att2 = (const float*)d_in[17];
    const float* bo2  = (const float*)d_in[18];
    const float* W5   = (const float*)d_in[19];
    const float* b5   = (const float*)d_in[20];
    const float* We1  = (const float*)d_in[21];
    const float* be1  = (const float*)d_in[22];
    const float* We2  = (const float*)d_in[23];
    const float* be2  = (const float*)d_in[24];
    const float* We3  = (const float*)d_in[25];
    const float* be3  = (const float*)d_in[26];
    const int*   src  = (const int*)d_in[27];
    const int*   dst  = (const int*)d_in[28];
    float* out = (float*)d_out;

    float *ph, *pxl, *pxr, *pM1, *pM2, *pc2, *pU, *pV;
    int *pdeg;
    cudaGetSymbolAddress((void**)&ph,   g_h);
    cudaGetSymbolAddress((void**)&pxl,  g_xl);
    cudaGetSymbolAddress((void**)&pxr,  g_xr);
    cudaGetSymbolAddress((void**)&pM1,  g_M1);
    cudaGetSymbolAddress((void**)&pM2,  g_M2);
    cudaGetSymbolAddress((void**)&pc2,  g_c2);
    cudaGetSymbolAddress((void**)&pU,   g_U);
    cudaGetSymbolAddress((void**)&pV,   g_V);
    cudaGetSymbolAddress((void**)&pdeg, g_deg);

    // side streams + fork/join events (created once; capture-safe per R5/R11/R12 evidence)
    static cudaStream_t s2 = nullptr, s3 = nullptr;
    static cudaEvent_t evF = nullptr, evCSR = nullptr, evPrep = nullptr, evZero = nullptr;
    if (!s2) {
        cudaStreamCreateWithFlags(&s2, cudaStreamNonBlocking);
        cudaStreamCreateWithFlags(&s3, cudaStreamNonBlocking);
        cudaEventCreateWithFlags(&evF,    cudaEventDisableTiming);
        cudaEventCreateWithFlags(&evCSR,  cudaEventDisableTiming);
        cudaEventCreateWithFlags(&evPrep, cudaEventDisableTiming);
        cudaEventCreateWithFlags(&evZero, cudaEventDisableTiming);
    }

    const int NBLK = NN / 64;

    // fork
    cudaEventRecord(evF, 0);
    cudaStreamWaitEvent(s2, evF, 0);
    cudaStreamWaitEvent(s3, evF, 0);

    // s3: low-occupancy background zeroing of the 256 MB output (1 block/SM -> co-runs)
    k_zero_out<<<148, 256, 0, s3>>>((float4*)out);
    cudaEventRecord(evZero, s3);

    // s2: CSR build (for gat1), then M1/M2/c2 (for the last fused3)
    cudaMemsetAsync(pdeg, 0, NN * sizeof(int), s2);
    k_edge0<<<EE / 256, 256, 0, s2>>>(src, dst);
    k_scan<<<1, 1024, 0, s2>>>();
    k_scatter<<<(EP + 255) / 256, 256, 0, s2>>>(src, dst);
    cudaEventRecord(evCSR, s2);
    k_prep<<<16, 256, 0, s2>>>(We1, be1, We2, be2);
    cudaEventRecord(evPrep, s2);

    // stream 0: node MLP + GAT-1 projections
    k_in<<<NBLK, 256>>>(x, W1, b1, W2, b2, ph);
    k_fused3<false, false><<<NBLK, 256>>>(ph, nullptr, nullptr, Wl1, bl1, Wr1, br1,
                                          nullptr, pxl, pxr);

    // join 1: gat needs only the CSR
    cudaStreamWaitEvent(0, evCSR, 0);
    k_gat<<<NN * 32 / 256, 256>>>(att1, bo1);

    // h += relu(hW4+b4) fused with GAT-2 projections
    k_fused3<true, true><<<NBLK, 256>>>(ph, W4, b4, Wl2, bl2, Wr2, br2,
                                        ph, pxl, pxr);
    k_gat<<<NN * 32 / 256, 256>>>(att2, bo2);

    // join 2: last fused3 consumes M1/M2/c2
    cudaStreamWaitEvent(0, evPrep, 0);
    k_fused3<true, false><<<NBLK, 256>>>(ph, W5, b5, pM1, pc2, pM2, nullptr,
                                         nullptr, pU, pV);

    // join 3: output fully zeroed -> scatter edge sigmoids only
    cudaStreamWaitEvent(0, evZero, 0);
    k_final_e<<<EE / 16, 256>>>(src, dst, We3, be3, out);
}

// round 17
// speedup vs baseline: 1.1178x; 1.1178x over previous
#include <cuda_runtime.h>
#include <math.h>

#define NN 8192
#define DD 64
#define EE 524288
#define EP (EE + NN)   // edges + self loops

// ---------------- scratch (device globals) ----------------
__device__ float g_h  [NN*DD];
__device__ float g_xl [NN*DD];
__device__ float g_xr [NN*DD];
__device__ float g_M1 [DD*DD];
__device__ float g_M2 [DD*DD];
__device__ float g_c2 [DD];
__device__ float g_U  [NN*DD];
__device__ float g_V  [NN*DD];
__device__ int   g_deg[NN];
__device__ int   g_cnt[NN];
__device__ int   g_off[NN + 1];
__device__ int   g_soff[NN + 1];
__device__ int   g_ce [EP];        // dst-CSR: source node per slot

// ---------------- 64x64(xK) GEMM micro-kernel on smem tiles ----------------
template<int K>
__device__ __forceinline__ void gemmK(const float sx[64][K + 1], const float* sW,
                                      const float* __restrict__ b,
                                      int tx, int ty, float acc[4][4])
{
    const float4 bb = b ? ((const float4*)b)[tx] : make_float4(0.f, 0.f, 0.f, 0.f);
#pragma unroll
    for (int i = 0; i < 4; i++) {
        acc[i][0] = bb.x; acc[i][1] = bb.y; acc[i][2] = bb.z; acc[i][3] = bb.w;
    }
#pragma unroll
    for (int k = 0; k < K; k++) {
        const float4 w = ((const float4*)sW)[k * 16 + tx];
        const float x0 = sx[ty*4 + 0][k];
        const float x1 = sx[ty*4 + 1][k];
        const float x2 = sx[ty*4 + 2][k];
        const float x3 = sx[ty*4 + 3][k];
        acc[0][0] = fmaf(x0, w.x, acc[0][0]); acc[0][1] = fmaf(x0, w.y, acc[0][1]);
        acc[0][2] = fmaf(x0, w.z, acc[0][2]); acc[0][3] = fmaf(x0, w.w, acc[0][3]);
        acc[1][0] = fmaf(x1, w.x, acc[1][0]); acc[1][1] = fmaf(x1, w.y, acc[1][1]);
        acc[1][2] = fmaf(x1, w.z, acc[1][2]); acc[1][3] = fmaf(x1, w.w, acc[1][3]);
        acc[2][0] = fmaf(x2, w.x, acc[2][0]); acc[2][1] = fmaf(x2, w.y, acc[2][1]);
        acc[2][2] = fmaf(x2, w.z, acc[2][2]); acc[2][3] = fmaf(x2, w.w, acc[2][3]);
        acc[3][0] = fmaf(x3, w.x, acc[3][0]); acc[3][1] = fmaf(x3, w.y, acc[3][1]);
        acc[3][2] = fmaf(x3, w.z, acc[3][2]); acc[3][3] = fmaf(x3, w.w, acc[3][3]);
    }
}

// ---------------- input MLP, fused: h = relu(xW1+b1) ; h += relu(hW2+b2) ----------------
__global__ __launch_bounds__(256) void k_in(const float* __restrict__ x,
                                            const float* __restrict__ W1, const float* __restrict__ b1,
                                            const float* __restrict__ W2, const float* __restrict__ b2,
                                            float* __restrict__ h_out)
{
    __shared__ float sx[64][13];
    __shared__ float sW1[12 * 64];
    __shared__ float st[64][65];
    __shared__ float sW2[64 * 64];
    const int tid = threadIdx.x;
    const int tx = tid & 15, ty = tid >> 4;
    const int nb = blockIdx.x * 64;

    for (int i = tid; i < 192; i += 256) {
        const float4 v = ((const float4*)x)[nb * 3 + i];
        const int n = i / 3, k = (i % 3) * 4;
        sx[n][k] = v.x; sx[n][k+1] = v.y; sx[n][k+2] = v.z; sx[n][k+3] = v.w;
    }
    for (int i = tid; i < 192; i += 256) ((float4*)sW1)[i] = ((const float4*)W1)[i];
    for (int i = tid; i < 1024; i += 256) ((float4*)sW2)[i] = ((const float4*)W2)[i];
    __syncthreads();

    float acc[4][4];
    gemmK<12>(sx, sW1, b1, tx, ty, acc);
#pragma unroll
    for (int i = 0; i < 4; i++)
#pragma unroll
        for (int j = 0; j < 4; j++)
            st[ty*4 + i][tx*4 + j] = fmaxf(acc[i][j], 0.f);
    __syncthreads();

    float acc2[4][4];
    gemmK<64>(st, sW2, b2, tx, ty, acc2);
#pragma unroll
    for (int i = 0; i < 4; i++) {
        float4 r;
        r.x = st[ty*4+i][tx*4+0] + fmaxf(acc2[i][0], 0.f);
        r.y = st[ty*4+i][tx*4+1] + fmaxf(acc2[i][1], 0.f);
        r.z = st[ty*4+i][tx*4+2] + fmaxf(acc2[i][2], 0.f);
        r.w = st[ty*4+i][tx*4+3] + fmaxf(acc2[i][3], 0.f);
        ((float4*)h_out)[(nb + ty*4 + i) * 16 + tx] = r;
    }
}

// ---------------- fused: [h' = h + relu(hWa+ba)] ; xl = h'Wl+bl ; xr = h'Wr+br ----------------
template<bool PRE, bool WRITE_H>
__global__ __launch_bounds__(256) void k_fused3(
    const float* __restrict__ h_in,
    const float* __restrict__ Wa, const float* __restrict__ ba,
    const float* __restrict__ Wl, const float* __restrict__ bl,
    const float* __restrict__ Wr, const float* __restrict__ br,
    float* __restrict__ h_out, float* __restrict__ xl_out, float* __restrict__ xr_out)
{
    __shared__ float sh[64][65];
    __shared__ float sW[64 * 64];                  // staged: Wa -> Wl -> Wr
    const int tid = threadIdx.x;
    const int tx = tid & 15, ty = tid >> 4;
    const int nb = blockIdx.x * 64;

    for (int i = tid; i < 1024; i += 256) {
        const float4 v = ((const float4*)h_in)[nb * 16 + i];
        const int n = i >> 4, k = (i & 15) * 4;
        sh[n][k] = v.x; sh[n][k+1] = v.y; sh[n][k+2] = v.z; sh[n][k+3] = v.w;
    }

    if (PRE) {
        for (int i = tid; i < 1024; i += 256) ((float4*)sW)[i] = ((const float4*)Wa)[i];
        __syncthreads();
        float acc[4][4];
        gemmK<64>(sh, sW, ba, tx, ty, acc);
        float hp[4][4];
#pragma unroll
        for (int i = 0; i < 4; i++)
#pragma unroll
            for (int j = 0; j < 4; j++)
                hp[i][j] = sh[ty*4 + i][tx*4 + j] + fmaxf(acc[i][j], 0.f);
        __syncthreads();
#pragma unroll
        for (int i = 0; i < 4; i++) {
#pragma unroll
            for (int j = 0; j < 4; j++) sh[ty*4 + i][tx*4 + j] = hp[i][j];
            if (WRITE_H)
                ((float4*)h_out)[(nb + ty*4 + i) * 16 + tx] =
                    make_float4(hp[i][0], hp[i][1], hp[i][2], hp[i][3]);
        }
    }

    __syncthreads();
    for (int i = tid; i < 1024; i += 256) ((float4*)sW)[i] = ((const float4*)Wl)[i];
    __syncthreads();
    {
        float acc[4][4];
        gemmK<64>(sh, sW, bl, tx, ty, acc);
#pragma unroll
        for (int i = 0; i < 4; i++)
            ((float4*)xl_out)[(nb + ty*4 + i) * 16 + tx] =
                make_float4(acc[i][0], acc[i][1], acc[i][2], acc[i][3]);
    }
    __syncthreads();
    for (int i = tid; i < 1024; i += 256) ((float4*)sW)[i] = ((const float4*)Wr)[i];
    __syncthreads();
    {
        float acc[4][4];
        gemmK<64>(sh, sW, br, tx, ty, acc);
#pragma unroll
        for (int i = 0; i < 4; i++)
            ((float4*)xr_out)[(nb + ty*4 + i) * 16 + tx] =
                make_float4(acc[i][0], acc[i][1], acc[i][2], acc[i][3]);
    }
}

// ---------------- M1 = We1[:64]@We2, M2 = We1[64:]@We2, c2 = be1@We2 + be2 ----------------
__global__ __launch_bounds__(256) void k_prep(const float* __restrict__ We1,
                                              const float* __restrict__ be1,
                                              const float* __restrict__ We2,
                                              const float* __restrict__ be2)
{
    __shared__ float sW2[64 * 64];
    __shared__ float sA[4 * 64];
    __shared__ float sB[4 * 64];
    const int tid = threadIdx.x;
    const int kb = blockIdx.x * 4;
    for (int i = tid; i < 1024; i += 256) ((float4*)sW2)[i] = ((const float4*)We2)[i];
    {
        const int kk = tid >> 6, c = tid & 63;
        sA[tid] = We1[(kb + kk) * 64 + c];
        sB[tid] = We1[(64 + kb + kk) * 64 + c];
    }
    __syncthreads();
    const int kk = tid >> 6, c = tid & 63;
    float a1 = 0.f, a2 = 0.f;
#pragma unroll
    for (int j = 0; j < 64; j++) {
        const float w2 = sW2[j * 64 + c];
        a1 = fmaf(sA[kk * 64 + j], w2, a1);
        a2 = fmaf(sB[kk * 64 + j], w2, a2);
    }
    g_M1[(kb + kk) * 64 + c] = a1;
    g_M2[(kb + kk) * 64 + c] = a2;
    if (blockIdx.x == 0 && tid < 64) {
        float s = be2[tid];
        for (int j = 0; j < 64; j++) s = fmaf(be1[j], sW2[j * 64 + tid], s);
        g_c2[tid] = s;
    }
}

// ---------------- edge pass 0: dst histogram + src row offsets (src sorted) ----------------
__global__ void k_edge0(const int* __restrict__ src, const int* __restrict__ dst)
{
    const int e = blockIdx.x * blockDim.x + threadIdx.x;
    if (e >= EE) return;
    atomicAdd(&g_deg[dst[e]], 1);
    const int a = src[e];
    const int b = (e + 1 < EE) ? src[e + 1] : NN;
    for (int r = a + 1; r <= b; r++) g_soff[r] = e + 1;   // lower_bound semantics
    if (e == 0) for (int r = 0; r <= a; r++) g_soff[r] = 0;
}

__global__ __launch_bounds__(1024) void k_scan()
{
    __shared__ int wsum[32];
    const int tid = threadIdx.x;
    int loc[8]; int s = 0;
#pragma unroll
    for (int j = 0; j < 8; j++) {
        loc[j] = g_deg[tid * 8 + j] + 1; s += loc[j];     // +1 self loop
        g_cnt[tid * 8 + j] = 0;                           // zero scatter counters here
    }
    const int lane = tid & 31, wid = tid >> 5;
    int v = s;
#pragma unroll
    for (int o = 1; o < 32; o <<= 1) {
        const int t = __shfl_up_sync(0xffffffffu, v, o);
        if (lane >= o) v += t;
    }
    if (lane == 31) wsum[wid] = v;
    __syncthreads();
    if (wid == 0) {
        int w = wsum[lane];
#pragma unroll
        for (int o = 1; o < 32; o <<= 1) {
            const int t = __shfl_up_sync(0xffffffffu, w, o);
            if (lane >= o) w += t;
        }
        wsum[lane] = w;
    }
    __syncthreads();
    int base = v - s + (wid ? wsum[wid - 1] : 0);
#pragma unroll
    for (int j = 0; j < 8; j++) { g_off[tid * 8 + j] = base; base += loc[j]; }
    if (tid == 1023) g_off[NN] = base;
}

__global__ void k_scatter(const int* __restrict__ src, const int* __restrict__ dst)
{
    const int e = blockIdx.x * blockDim.x + threadIdx.x;
    if (e >= EP) return;
    int s, d;
    if (e < EE) { s = src[e]; d = dst[e]; } else { s = d = e - EE; }
    const int pos = atomicAdd(&g_cnt[d], 1);
    g_ce[g_off[d] + pos] = s;
}

// ---------------- fused GATv2 layer: one warp per dst node, single pass, no atomics ----------------
__global__ __launch_bounds__(256) void k_gat(const float* __restrict__ att,
                                             const float* __restrict__ bo)
{
    const int w = (blockIdx.x * 256 + threadIdx.x) >> 5;   // grid covers NN exactly
    const int lane = threadIdx.x & 31;
    const int d = w;
    const float2 xr = ((const float2*)g_xr)[d * 32 + lane];
    const float2 a  = ((const float2*)att)[lane];
    const int beg = g_off[d], end = g_off[d + 1];   // warp-uniform
    float accx = 0.f, accy = 0.f, den = 0.f;
#pragma unroll 4
    for (int i = beg; i < end; i++) {
        const int s = g_ce[i];
        const float2 vl = ((const float2*)g_xl)[s * 32 + lane];
        float t0 = vl.x + xr.x; t0 = t0 > 0.f ? t0 : 0.2f * t0;
        float t1 = vl.y + xr.y; t1 = t1 > 0.f ? t1 : 0.2f * t1;
        float v = t0 * a.x + t1 * a.y;
        v += __shfl_xor_sync(0xffffffffu, v, 1);
        v += __shfl_xor_sync(0xffffffffu, v, 2);
        v += __shfl_xor_sync(0xffffffffu, v, 4);   // per-head logit in each 8-lane group
        const float pe = __expf(v);                // softmax shift-invariant; logits small
        den  += pe;
        accx = fmaf(pe, vl.x, accx);
        accy = fmaf(pe, vl.y, accy);
    }
    const float inv = 1.0f / den;
    const int idx = d * 64 + 2 * lane;
    g_h[idx]     += accx * inv + bo[2 * lane];
    g_h[idx + 1] += accy * inv + bo[2 * lane + 1];
}

// ---------------- final: compose full output row in smem, single streaming write ----------------
// Warp-uniform edge-loop trip count; tail lanes predicated (all lanes run all shuffles).
__global__ __launch_bounds__(256) void k_final_row(const int* __restrict__ dst,
                                                   const float* __restrict__ We3,
                                                   const float* __restrict__ be3,
                                                   float* __restrict__ out)
{
    const int s = blockIdx.x;
    __shared__ float srow[NN];          // 32 KB: the full output row
    __shared__ float su[64];
    const int tid = threadIdx.x;
    if (tid < 64) su[tid] = g_U[s * 64 + tid];

    // zero the smem row
    {
        const float4 z = make_float4(0.f, 0.f, 0.f, 0.f);
        for (int i = tid; i < NN / 4; i += 256) ((float4*)srow)[i] = z;
    }
    __syncthreads();

    // scatter this row's edge sigmoids into smem (16 groups of 16 lanes)
    const int lo = g_soff[s], hi = g_soff[s + 1];
    const int cnt = hi - lo;
    const int nIter = (cnt + 15) >> 4;              // uniform across the block
    const int g = tid >> 4, l = tid & 15;
    const float4 w3 = ((const float4*)We3)[l];
    const float4 u  = make_float4(su[l*4], su[l*4+1], su[l*4+2], su[l*4+3]);
    const float b3 = be3[0];
    for (int it = 0; it < nIter; it++) {
        const int eidx = g + it * 16;
        const bool valid = eidx < cnt;
        const int d = valid ? dst[lo + eidx] : 0;
        const float4 vv = ((const float4*)g_V)[d * 16 + l];
        float v = fmaxf(u.x + vv.x, 0.f) * w3.x
                + fmaxf(u.y + vv.y, 0.f) * w3.y
                + fmaxf(u.z + vv.z, 0.f) * w3.z
                + fmaxf(u.w + vv.w, 0.f) * w3.w;
        v += __shfl_xor_sync(0xffffffffu, v, 1);
        v += __shfl_xor_sync(0xffffffffu, v, 2);
        v += __shfl_xor_sync(0xffffffffu, v, 4);
        v += __shfl_xor_sync(0xffffffffu, v, 8);   // reduce within 16-lane group
        if (l == 0 && valid) srow[d] = 1.0f / (1.0f + __expf(-(v + b3)));
    }
    __syncthreads();

    // single coalesced streaming write of the whole row (touches DRAM exactly once)
    float4* row = (float4*)(out + (long)s * NN);
    for (int i = tid; i < NN / 4; i += 256)
        __stcs(&row[i], ((const float4*)srow)[i]);
}

// ---------------- host ----------------
extern "C" void kernel_launch(void* const* d_in, const int* in_sizes, int n_in,
                              void* d_out, int out_size)
{
    const float* x    = (const float*)d_in[0];
    const float* W1   = (const float*)d_in[1];
    const float* b1   = (const float*)d_in[2];
    const float* W2   = (const float*)d_in[3];
    const float* b2   = (const float*)d_in[4];
    const float* Wl1  = (const float*)d_in[5];
    const float* bl1  = (const float*)d_in[6];
    const float* Wr1  = (const float*)d_in[7];
    const float* br1  = (const float*)d_in[8];
    const float* att1 = (const float*)d_in[9];
    const float* bo1  = (const float*)d_in[10];
    const float* W4   = (const float*)d_in[11];
    const float* b4   = (const float*)d_in[12];
    const float* Wl2  = (const float*)d_in[13];
    const float* bl2  = (const float*)d_in[14];
    const float* Wr2  = (const float*)d_in[15];
    const float* br2  = (const float*)d_in[16];
    const float* att2 = (const float*)d_in[17];
    const float* bo2  = (const float*)d_in[18];
    const float* W5   = (const float*)d_in[19];
    const float* b5   = (const float*)d_in[20];
    const float* We1  = (const float*)d_in[21];
    const float* be1  = (const float*)d_in[22];
    const float* We2  = (const float*)d_in[23];
    const float* be2  = (const float*)d_in[24];
    const float* We3  = (const float*)d_in[25];
    const float* be3  = (const float*)d_in[26];
    const int*   src  = (const int*)d_in[27];
    const int*   dst  = (const int*)d_in[28];
    float* out = (float*)d_out;

    float *ph, *pxl, *pxr, *pM1, *pM2, *pc2, *pU, *pV;
    int *pdeg;
    cudaGetSymbolAddress((void**)&ph,   g_h);
    cudaGetSymbolAddress((void**)&pxl,  g_xl);
    cudaGetSymbolAddress((void**)&pxr,  g_xr);
    cudaGetSymbolAddress((void**)&pM1,  g_M1);
    cudaGetSymbolAddress((void**)&pM2,  g_M2);
    cudaGetSymbolAddress((void**)&pc2,  g_c2);
    cudaGetSymbolAddress((void**)&pU,   g_U);
    cudaGetSymbolAddress((void**)&pV,   g_V);
    cudaGetSymbolAddress((void**)&pdeg, g_deg);

    // side stream + fork/join events (created once; capture-safe per R5/R11/R12 evidence)
    static cudaStream_t s2 = nullptr;
    static cudaEvent_t evF = nullptr, evCSR = nullptr, evPrep = nullptr;
    if (!s2) {
        cudaStreamCreateWithFlags(&s2, cudaStreamNonBlocking);
        cudaEventCreateWithFlags(&evF,    cudaEventDisableTiming);
        cudaEventCreateWithFlags(&evCSR,  cudaEventDisableTiming);
        cudaEventCreateWithFlags(&evPrep, cudaEventDisableTiming);
    }

    const int NBLK = NN / 64;

    // fork: side stream builds CSR (needed by gat1), then M1/M2/c2 (needed only by the last fused3)
    cudaEventRecord(evF, 0);
    cudaStreamWaitEvent(s2, evF, 0);
    cudaMemsetAsync(pdeg, 0, NN * sizeof(int), s2);
    k_edge0<<<EE / 256, 256, 0, s2>>>(src, dst);
    k_scan<<<1, 1024, 0, s2>>>();
    k_scatter<<<(EP + 255) / 256, 256, 0, s2>>>(src, dst);
    cudaEventRecord(evCSR, s2);
    k_prep<<<16, 256, 0, s2>>>(We1, be1, We2, be2);
    cudaEventRecord(evPrep, s2);

    // stream 0: node MLP + GAT-1 projections (independent of CSR/prep)
    k_in<<<NBLK, 256>>>(x, W1, b1, W2, b2, ph);
    k_fused3<false, false><<<NBLK, 256>>>(ph, nullptr, nullptr, Wl1, bl1, Wr1, br1,
                                          nullptr, pxl, pxr);

    // join 1: gat needs only the CSR; k_prep keeps running concurrently on s2
    cudaStreamWaitEvent(0, evCSR, 0);
    k_gat<<<NN * 32 / 256, 256>>>(att1, bo1);

    // h += relu(hW4+b4) fused with GAT-2 projections
    k_fused3<true, true><<<NBLK, 256>>>(ph, W4, b4, Wl2, bl2, Wr2, br2,
                                        ph, pxl, pxr);
    k_gat<<<NN * 32 / 256, 256>>>(att2, bo2);

    // join 2: last fused3 consumes M1/M2/c2 (k_prep finished long ago)
    cudaStreamWaitEvent(0, evPrep, 0);
    k_fused3<true, false><<<NBLK, 256>>>(ph, W5, b5, pM1, pc2, pM2, nullptr,
                                         nullptr, pU, pV);

    // per-row output: compose row in smem, write once
    k_final_row<<<NN, 256>>>(dst, We3, be3, out);
}